// round 16
// baseline (speedup 1.0000x reference)
#include <cuda_runtime.h>
#include <cuda_fp16.h>
#include <cstdint>

#define N_AG  1024
#define HID   128
#define KDIM  2048
#define OUTD  128
#define CELLS 1024
#define NKS   16            // split-K slices (128 k each)

// ---- scratch (device globals; no allocs allowed) ----
__device__ __align__(16) __half g_flat[N_AG * KDIM];   // 4 MB pooled features (fp16)
__device__ float g_part[NKS * N_AG * OUTD];            // 8 MB split-K partials

__device__ __forceinline__ uint32_t smem_u32(const void* p) {
    uint32_t a;
    asm("{ .reg .u64 t; cvta.to.shared.u64 t, %1; cvt.u32.u64 %0, t; }" : "=r"(a) : "l"(p));
    return a;
}
__device__ __forceinline__ void griddep_wait() {
    asm volatile("griddepcontrol.wait;" ::: "memory");
}
__device__ __forceinline__ void griddep_launch() {
    asm volatile("griddepcontrol.launch_dependents;" ::: "memory");
}
__device__ __forceinline__ void ldsm_x4(uint32_t& r0, uint32_t& r1, uint32_t& r2, uint32_t& r3,
                                        uint32_t addr) {
    asm volatile("ldmatrix.sync.aligned.m8n8.x4.shared.b16 {%0,%1,%2,%3}, [%4];"
                 : "=r"(r0), "=r"(r1), "=r"(r2), "=r"(r3) : "r"(addr));
}
__device__ __forceinline__ void mma16816_f16(float* c, const uint32_t* a, const uint32_t* b) {
    asm volatile("mma.sync.aligned.m16n8k16.row.col.f32.f16.f16.f32 "
                 "{%0,%1,%2,%3}, {%4,%5,%6,%7}, {%8,%9}, {%0,%1,%2,%3};"
                 : "+f"(c[0]), "+f"(c[1]), "+f"(c[2]), "+f"(c[3])
                 : "r"(a[0]), "r"(a[1]), "r"(a[2]), "r"(a[3]), "r"(b[0]), "r"(b[1]));
}
__device__ __forceinline__ void cp_async16(uint32_t dst, const void* src) {
    asm volatile("cp.async.cg.shared.global [%0], [%1], 16;" :: "r"(dst), "l"(src) : "memory");
}

// ============ kernel 1: scatter + pool -> flat (fp16), 1 CTA/ego =============
// Set-semantics winner grid (max j wins == XLA scatter update order), compact,
// accumulate pooled[16][128] fp32 (2 entry streams to halve the serial chain),
// emit flat[i][h*16+blk] = pooled[blk][h] as fp16.
__global__ void __launch_bounds__(256) flat_kernel(const float* __restrict__ obs2,
                                                   const float* __restrict__ Hs) {
    __shared__ int   w[CELLS];
    __shared__ int   se[CELLS];
    __shared__ int   s_cnt;
    __shared__ float pooled[2][16][129];    // padded: conflict-free transpose read
    const int i = blockIdx.x;
    const int t = threadIdx.x;              // 256

    griddep_launch();                       // gemm may start its W-convert now

    for (int c = t; c < CELLS; c += 256) w[c] = -1;
    for (int q = t; q < 2 * 16 * 129; q += 256) (&pooled[0][0][0])[q] = 0.0f;
    if (t == 0) s_cnt = 0;
    const float2 oi = ((const float2*)obs2)[i];
    __syncthreads();

    int cnt = 0;
    if (oi.x == oi.x) {                     // ego not NaN (uniform branch)
        for (int j = t; j < N_AG; j += 256) {
            if (j == i) continue;
            float2 oj = ((const float2*)obs2)[j];
            if (oj.x != oj.x) continue;     // neighbor NaN
            float ox = (oj.x - oi.x) * 4.0f + 16.0f;   // exact pow2 scale
            float oy = (oj.y - oi.y) * 4.0f + 16.0f;
            if (ox >= 0.0f && ox < 32.0f && oy >= 0.0f && oy < 32.0f)
                atomicMax(&w[((int)ox) * 32 + (int)oy], j);
        }
        __syncthreads();
        for (int c = t; c < CELLS; c += 256) {
            int j = w[c];
            if (j >= 0) {
                int blk = ((c >> 8) << 2) | ((c & 31) >> 3);   // gi*4+gj
                int p = atomicAdd(&s_cnt, 1);
                se[p] = (j << 4) | blk;
            }
        }
        __syncthreads();
        cnt = s_cnt;
    }

    // accumulate: threads t<128 take even entries, t>=128 odd (separate bufs)
    {
        const int half = t >> 7, ch = t & 127;
        for (int e = half; e < cnt; e += 2) {
            int en = se[e];
            pooled[half][en & 15][ch] += Hs[(en >> 4) * HID + ch];
        }
    }
    __syncthreads();

    // write flat row: thread t -> k = t*8 .. t*8+7 (one uint4)
    {
        const int k0 = t * 8;
        __align__(16) __half hv[8];
#pragma unroll
        for (int s = 0; s < 8; s++) {
            int k = k0 + s, h = k >> 4, blk = k & 15;
            hv[s] = __float2half_rn(pooled[0][blk][h] + pooled[1][blk][h]);
        }
        *(uint4*)(g_flat + i * KDIM + k0) = *(const uint4*)&hv[0];
    }
}

// ===================== kernel 2: split-K mma.sync GEMM =======================
// part[ksl] = flat[:, k-chunk] @ W[:, k-chunk]^T.  grid (8 m, 16 ksl), 256 thr.
// W consumed in NATURAL layout (k = h*16+blk == W column); fp16 split on W:
// Bh = fp16(v), Bls = fp16((v-Bh)*2048); acc + accLo/2048 in epilogue.
#define LDS   136
#define TILE  (128 * LDS)
#define SMEM_DYN (3 * TILE * 2)            // 104448 B

__global__ void __launch_bounds__(256, 1) gemm_kernel(const float* __restrict__ W) {
    extern __shared__ __half sm[];
    __half* sA  = sm;                      // flat tile (fp16)
    __half* sBh = sm + TILE;
    __half* sBl = sm + 2 * TILE;

    const int t   = threadIdx.x;
    const int w   = t >> 5;
    const int l   = t & 31;
    const int m0  = blockIdx.x << 7;
    const int ksl = blockIdx.y;
    const int k0  = ksl << 7;
    const int wm  = (w >> 2) * 64;
    const int wn  = (w & 3) * 32;

    // ---- W chunk convert (independent of flat_kernel; overlaps it) ----
#pragma unroll
    for (int q = t; q < 4096; q += 256) {  // 128 n-rows x 32 float4
        int r = q >> 5, c = q & 31;
        float4 v = *(const float4*)(W + r * KDIM + k0 + c * 4);
        __align__(8) __half hi[4];
        __align__(8) __half lo[4];
        hi[0] = __float2half_rn(v.x); lo[0] = __float2half_rn((v.x - __half2float(hi[0])) * 2048.0f);
        hi[1] = __float2half_rn(v.y); lo[1] = __float2half_rn((v.y - __half2float(hi[1])) * 2048.0f);
        hi[2] = __float2half_rn(v.z); lo[2] = __float2half_rn((v.z - __half2float(hi[2])) * 2048.0f);
        hi[3] = __float2half_rn(v.w); lo[3] = __float2half_rn((v.w - __half2float(hi[3])) * 2048.0f);
        *(uint2*)(sBh + r * LDS + c * 4) = *(const uint2*)&hi[0];
        *(uint2*)(sBl + r * LDS + c * 4) = *(const uint2*)&lo[0];
    }

    griddep_wait();                        // flat_kernel complete -> g_flat visible

    // ---- flat tile (fp16, cp.async from L2) ----
#pragma unroll
    for (int q = t; q < 2048; q += 256) {  // 128 rows x 16 chunks of 16B
        int r = q >> 4, c = q & 15;
        cp_async16(smem_u32(sA + r * LDS + c * 8), g_flat + (m0 + r) * KDIM + k0 + c * 8);
    }
    asm volatile("cp.async.commit_group;" ::: "memory");
    asm volatile("cp.async.wait_group 0;" ::: "memory");
    __syncthreads();

    float acc[4][4][4], accLo[4][4][4];
#pragma unroll
    for (int mi = 0; mi < 4; mi++)
#pragma unroll
        for (int ni = 0; ni < 4; ni++)
#pragma unroll
            for (int q = 0; q < 4; q++) { acc[mi][ni][q] = 0.0f; accLo[mi][ni][q] = 0.0f; }

    const int aRow = wm + (l & 15);
    const int aCol = (l >> 4) * 8;
    const int bRow = wn + ((l >> 4) * 8) + (l & 7);
    const int bCol = ((l >> 3) & 1) * 8;

    const uint32_t aB  = smem_u32(sA  + aRow * LDS + aCol);
    const uint32_t bHB = smem_u32(sBh + bRow * LDS + bCol);
    const uint32_t bLB = smem_u32(sBl + bRow * LDS + bCol);

#pragma unroll
    for (int kk = 0; kk < 8; kk++) {
        const uint32_t ko = kk * 32;       // kk*16 elements * 2B
        uint32_t aF[4][4], bH[4][2], bL[4][2];
#pragma unroll
        for (int mi = 0; mi < 4; mi++)
            ldsm_x4(aF[mi][0], aF[mi][1], aF[mi][2], aF[mi][3],
                    aB + mi * (16 * LDS * 2) + ko);
#pragma unroll
        for (int bi = 0; bi < 2; bi++) {
            ldsm_x4(bH[2 * bi][0], bH[2 * bi][1], bH[2 * bi + 1][0], bH[2 * bi + 1][1],
                    bHB + bi * (16 * LDS * 2) + ko);
            ldsm_x4(bL[2 * bi][0], bL[2 * bi][1], bL[2 * bi + 1][0], bL[2 * bi + 1][1],
                    bLB + bi * (16 * LDS * 2) + ko);
        }
#pragma unroll
        for (int mi = 0; mi < 4; mi++)
#pragma unroll
            for (int ni = 0; ni < 4; ni++) {
                mma16816_f16(acc[mi][ni],   aF[mi], bH[ni]);
                mma16816_f16(accLo[mi][ni], aF[mi], bL[ni]);
            }
    }

    float* pb = g_part + ksl * (N_AG * OUTD);
    const float s = 1.0f / 2048.0f;
    const int g2 = l >> 2, tig = l & 3;
#pragma unroll
    for (int mi = 0; mi < 4; mi++) {
        const int row = m0 + wm + mi * 16 + g2;
#pragma unroll
        for (int ni = 0; ni < 4; ni++) {
            const int col = wn + ni * 8 + tig * 2;
            *(float2*)(pb + row * OUTD + col) =
                make_float2(acc[mi][ni][0] + accLo[mi][ni][0] * s,
                            acc[mi][ni][1] + accLo[mi][ni][1] * s);
            *(float2*)(pb + (row + 8) * OUTD + col) =
                make_float2(acc[mi][ni][2] + accLo[mi][ni][2] * s,
                            acc[mi][ni][3] + accLo[mi][ni][3] * s);
        }
    }
    // implicit launch_dependents at exit
}

// ===================== kernel 3: split-K reduce + bias + ReLU ================
__global__ void __launch_bounds__(256) biasrelu_kernel(const float* __restrict__ b,
                                                       float* __restrict__ out) {
    griddep_wait();
    const int idx = blockIdx.x * 256 + threadIdx.x;    // 32768 float4s
    float4 s = make_float4(0.f, 0.f, 0.f, 0.f);
#pragma unroll
    for (int ks = 0; ks < NKS; ks++) {
        float4 v = ((const float4*)(g_part + ks * (N_AG * OUTD)))[idx];
        s.x += v.x; s.y += v.y; s.z += v.z; s.w += v.w;
    }
    float4 bv = ((const float4*)b)[idx & 31];          // 32 float4 per out row
    s.x = fmaxf(s.x + bv.x, 0.f);
    s.y = fmaxf(s.y + bv.y, 0.f);
    s.z = fmaxf(s.z + bv.z, 0.f);
    s.w = fmaxf(s.w + bv.w, 0.f);
    ((float4*)out)[idx] = s;
}

// =============================================================================
extern "C" void kernel_launch(void* const* d_in, const int* in_sizes, int n_in,
                              void* d_out, int out_size) {
    const float* hidden = (const float*)d_in[0];
    const float* obs2   = (const float*)d_in[2];
    const float* W      = (const float*)d_in[3];
    const float* b      = (const float*)d_in[4];
    float*       out    = (float*)d_out;

    cudaFuncSetAttribute(gemm_kernel, cudaFuncAttributeMaxDynamicSharedMemorySize, SMEM_DYN);

    flat_kernel<<<N_AG, 256>>>(obs2, hidden);

    cudaLaunchAttribute attr[1];
    attr[0].id = cudaLaunchAttributeProgrammaticStreamSerialization;
    attr[0].val.programmaticStreamSerializationAllowed = 1;

    cudaLaunchConfig_t cfg = {};
    cfg.gridDim = dim3(N_AG / 128, NKS);   // (8, 16) = 128 CTAs
    cfg.blockDim = dim3(256);
    cfg.dynamicSmemBytes = SMEM_DYN;
    cfg.stream = 0;
    cfg.attrs = attr;
    cfg.numAttrs = 1;
    cudaLaunchKernelEx(&cfg, gemm_kernel, W);

    cfg.gridDim = dim3(N_AG * OUTD / 4 / 256);   // 128
    cfg.dynamicSmemBytes = 0;
    cudaLaunchKernelEx(&cfg, biasrelu_kernel, b, out);
}

// round 17
// speedup vs baseline: 1.2262x; 1.2262x over previous
#include <cuda_runtime.h>
#include <cuda_fp16.h>
#include <cstdint>

#define N_AG  1024
#define HID   128
#define KDIM  2048
#define OUTD  128
#define CELLS 1024

// ---- scratch (device globals; no allocs allowed) ----
__device__ __align__(16) __half g_Bh[KDIM * HID];    // Wperm hi (fp16)
__device__ __align__(16) __half g_Bls[KDIM * HID];   // Wperm lo * 2^11 (fp16)
__device__ float g_P[N_AG * KDIM];                   // 8 MB projections

__device__ __forceinline__ uint32_t smem_u32(const void* p) {
    uint32_t a;
    asm("{ .reg .u64 t; cvta.to.shared.u64 t, %1; cvt.u32.u64 %0, t; }" : "=r"(a) : "l"(p));
    return a;
}
__device__ __forceinline__ void griddep_wait() {
    asm volatile("griddepcontrol.wait;" ::: "memory");
}
__device__ __forceinline__ void griddep_launch() {
    asm volatile("griddepcontrol.launch_dependents;" ::: "memory");
}
__device__ __forceinline__ void ldsm_x4(uint32_t& r0, uint32_t& r1, uint32_t& r2, uint32_t& r3,
                                        uint32_t addr) {
    asm volatile("ldmatrix.sync.aligned.m8n8.x4.shared.b16 {%0,%1,%2,%3}, [%4];"
                 : "=r"(r0), "=r"(r1), "=r"(r2), "=r"(r3) : "r"(addr));
}
__device__ __forceinline__ void mma16816_f16(float* c, const uint32_t* a, const uint32_t* b) {
    asm volatile("mma.sync.aligned.m16n8k16.row.col.f32.f16.f16.f32 "
                 "{%0,%1,%2,%3}, {%4,%5,%6,%7}, {%8,%9}, {%0,%1,%2,%3};"
                 : "+f"(c[0]), "+f"(c[1]), "+f"(c[2]), "+f"(c[3])
                 : "r"(a[0]), "r"(a[1]), "r"(a[2]), "r"(a[3]), "r"(b[0]), "r"(b[1]));
}
__device__ __forceinline__ void cp_async16(uint32_t dst, const void* src) {
    asm volatile("cp.async.cg.shared.global [%0], [%1], 16;" :: "r"(dst), "l"(src) : "memory");
}

// ======================= prep kernel: convW only =============================
// 256 CTAs: tiled transpose W[n][h*16+blk] -> Wperm[blk*128+n][h],
// fp16 split: Bh = fp16(v), Bls = fp16((v - Bh) * 2048).
#define NT 4       // n rows per tile
#define KT 256     // k cols per tile

__global__ void __launch_bounds__(256) prep_kernel(const float* __restrict__ W) {
    __shared__ float cw[NT][KT + 1];     // ~4.1 KB
    const int b0 = blockIdx.x;
    const int t  = threadIdx.x;   // 256

    griddep_launch();             // gemm may start its A-convert immediately

    const int nt = b0 >> 3, kt = b0 & 7;
    const int n0 = nt * NT, k0 = kt * KT, h0 = kt * 16;
    {   // load 4x256 fp32 tile: 1 float4 per thread (scalar STS: 257 stride)
        int r = t >> 6, c4 = t & 63;
        float4 v = *(const float4*)(W + (n0 + r) * KDIM + k0 + c4 * 4);
        cw[r][c4 * 4 + 0] = v.x;
        cw[r][c4 * 4 + 1] = v.y;
        cw[r][c4 * 4 + 2] = v.z;
        cw[r][c4 * 4 + 3] = v.w;
    }
    __syncthreads();
    if (t < 64) {                 // 64 (blk,nn) rows, 16 h values each
        const int blk = t >> 2, nn = t & 3;
        const int r = (blk << 7) | (n0 + nn);
        __align__(16) __half hi[16];
        __align__(16) __half lo[16];
#pragma unroll
        for (int hr = 0; hr < 16; hr++) {
            float v = cw[nn][hr * 16 + blk];
            hi[hr] = __float2half_rn(v);
            lo[hr] = __float2half_rn((v - __half2float(hi[hr])) * 2048.0f);
        }
        *(uint4*)(g_Bh  + r * HID + h0)     = *(const uint4*)&hi[0];
        *(uint4*)(g_Bh  + r * HID + h0 + 8) = *(const uint4*)&hi[8];
        *(uint4*)(g_Bls + r * HID + h0)     = *(const uint4*)&lo[0];
        *(uint4*)(g_Bls + r * HID + h0 + 8) = *(const uint4*)&lo[8];
    }
}

// ============================ mma.sync GEMM ==================================
// P = hidden(1024x128) @ Wperm^T(2048x128). grid(8,16), 256 thr, 128x128 tile.
// 2 fp16 passes: acc = Ah*Bh, accLo = Ah*(Bl*2^11); P = acc + accLo/2048.
// B loaded in 2 k-halves (cp.async groups) pipelined against the MMA.
#define LDS   136
#define TILE  (128 * LDS)
#define SMEM_DYN (3 * TILE * 2)            // 104448 B

__global__ void __launch_bounds__(256, 1) gemm_mma_kernel(const float* __restrict__ Hs) {
    extern __shared__ __half sm[];
    __half* sAh = sm;
    __half* sBh = sm + TILE;
    __half* sBl = sm + 2 * TILE;

    const int t  = threadIdx.x;
    const int w  = t >> 5;
    const int l  = t & 31;
    const int m0 = blockIdx.x << 7;
    const int n0 = blockIdx.y << 7;
    const int wm = (w >> 2) * 64;
    const int wn = (w & 3) * 32;

    // ---- A convert: hidden fp32 -> fp16 hi in smem (no dependency) ----
#pragma unroll
    for (int q = t; q < 4096; q += 256) {  // 128 rows x 32 float4
        int r = q >> 5, c = q & 31;
        float4 v = *(const float4*)(Hs + (m0 + r) * HID + c * 4);
        __align__(8) __half hi[4];
        hi[0] = __float2half_rn(v.x);
        hi[1] = __float2half_rn(v.y);
        hi[2] = __float2half_rn(v.z);
        hi[3] = __float2half_rn(v.w);
        *(uint2*)(sAh + r * LDS + c * 4) = *(const uint2*)&hi[0];
    }

    griddep_launch();             // let out_kernel start its scatter
    griddep_wait();               // prep complete -> g_Bh/g_Bls visible

    // ---- B tiles: 2 cp.async groups (k halves 0-63 / 64-127) ----
#pragma unroll
    for (int q = t; q < 1024; q += 256) {  // half 0: chunks c 0..7
        int r = q >> 3, c = q & 7;
        cp_async16(smem_u32(sBh + r * LDS + c * 8), g_Bh  + (n0 + r) * HID + c * 8);
        cp_async16(smem_u32(sBl + r * LDS + c * 8), g_Bls + (n0 + r) * HID + c * 8);
    }
    asm volatile("cp.async.commit_group;" ::: "memory");
#pragma unroll
    for (int q = t; q < 1024; q += 256) {  // half 1: chunks c 8..15
        int r = q >> 3, c = (q & 7) + 8;
        cp_async16(smem_u32(sBh + r * LDS + c * 8), g_Bh  + (n0 + r) * HID + c * 8);
        cp_async16(smem_u32(sBl + r * LDS + c * 8), g_Bls + (n0 + r) * HID + c * 8);
    }
    asm volatile("cp.async.commit_group;" ::: "memory");

    float acc[4][4][4], accLo[4][4][4];
#pragma unroll
    for (int mi = 0; mi < 4; mi++)
#pragma unroll
        for (int ni = 0; ni < 4; ni++)
#pragma unroll
            for (int q = 0; q < 4; q++) { acc[mi][ni][q] = 0.0f; accLo[mi][ni][q] = 0.0f; }

    const int aRow = wm + (l & 15);
    const int aCol = (l >> 4) * 8;
    const int bRow = wn + ((l >> 4) * 8) + (l & 7);
    const int bCol = ((l >> 3) & 1) * 8;

    const uint32_t aHB = smem_u32(sAh + aRow * LDS + aCol);
    const uint32_t bHB = smem_u32(sBh + bRow * LDS + bCol);
    const uint32_t bLB = smem_u32(sBl + bRow * LDS + bCol);

    asm volatile("cp.async.wait_group 1;" ::: "memory");   // half 0 ready
    __syncthreads();

#pragma unroll
    for (int kk = 0; kk < 8; kk++) {
        if (kk == 4) {                                     // half 1 ready
            asm volatile("cp.async.wait_group 0;" ::: "memory");
            __syncthreads();
        }
        const uint32_t ko = kk * 32;       // kk*16 elements * 2B
        uint32_t aH[4][4], bH[4][2], bL[4][2];
#pragma unroll
        for (int mi = 0; mi < 4; mi++)
            ldsm_x4(aH[mi][0], aH[mi][1], aH[mi][2], aH[mi][3],
                    aHB + mi * (16 * LDS * 2) + ko);
#pragma unroll
        for (int bi = 0; bi < 2; bi++) {
            ldsm_x4(bH[2 * bi][0], bH[2 * bi][1], bH[2 * bi + 1][0], bH[2 * bi + 1][1],
                    bHB + bi * (16 * LDS * 2) + ko);
            ldsm_x4(bL[2 * bi][0], bL[2 * bi][1], bL[2 * bi + 1][0], bL[2 * bi + 1][1],
                    bLB + bi * (16 * LDS * 2) + ko);
        }
#pragma unroll
        for (int mi = 0; mi < 4; mi++)
#pragma unroll
            for (int ni = 0; ni < 4; ni++) {
                mma16816_f16(acc[mi][ni],   aH[mi], bH[ni]);
                mma16816_f16(accLo[mi][ni], aH[mi], bL[ni]);
            }
    }

    const float s = 1.0f / 2048.0f;
    const int g2 = l >> 2, tig = l & 3;
#pragma unroll
    for (int mi = 0; mi < 4; mi++) {
        const int row = m0 + wm + mi * 16 + g2;
#pragma unroll
        for (int ni = 0; ni < 4; ni++) {
            const int col = n0 + wn + ni * 8 + tig * 2;
            *(float2*)(g_P + row * KDIM + col) =
                make_float2(acc[mi][ni][0] + accLo[mi][ni][0] * s,
                            acc[mi][ni][1] + accLo[mi][ni][1] * s);
            *(float2*)(g_P + (row + 8) * KDIM + col) =
                make_float2(acc[mi][ni][2] + accLo[mi][ni][2] * s,
                            acc[mi][ni][3] + accLo[mi][ni][3] * s);
        }
    }
}

// ================= fused scatter + output gather (512 thr) ===================
// One CTA per ego. Scatter (obs2 only, overlaps GEMM via PDL early-launch),
// then griddepcontrol.wait (gemm complete), then ONE round of P-row gathers.
__global__ void __launch_bounds__(512) out_kernel(const float* __restrict__ obs2,
                                                  const float* __restrict__ b,
                                                  float* __restrict__ out) {
    __shared__ int    w[CELLS];
    __shared__ int    se[CELLS];
    __shared__ int    s_cnt;
    __shared__ float4 sp[16][32];
    const int i = blockIdx.x;
    const int t = threadIdx.x;     // 512
    const int g = t >> 5, l = t & 31;   // 16 gather groups

    for (int c = t; c < CELLS; c += 512) w[c] = -1;
    if (t == 0) s_cnt = 0;
    const float2 oi = ((const float2*)obs2)[i];    // broadcast load
    __syncthreads();

    int cnt = 0;
    if (oi.x == oi.x) {                            // ego not NaN (uniform)
        for (int j = t; j < N_AG; j += 512) {      // obs2 L2-resident (8KB)
            if (j == i) continue;
            float2 oj = ((const float2*)obs2)[j];
            if (oj.x != oj.x) continue;            // neighbor NaN
            float ox = (oj.x - oi.x) * 4.0f + 16.0f;   // exact pow2 scale
            float oy = (oj.y - oi.y) * 4.0f + 16.0f;
            if (ox >= 0.0f && ox < 32.0f && oy >= 0.0f && oy < 32.0f)
                atomicMax(&w[((int)ox) * 32 + (int)oy], j);  // set-sem: max j
        }
        __syncthreads();
        for (int c = t; c < CELLS; c += 512) {
            int j = w[c];
            if (j >= 0) {
                int blk = ((c >> 8) << 2) | ((c & 31) >> 3);   // gi*4+gj
                int p = atomicAdd(&s_cnt, 1);
                se[p] = (j << 11) | (blk << 7);    // row offset into P
            }
        }
        __syncthreads();
        cnt = s_cnt;
    }

    griddep_wait();                                // gemm complete -> g_P visible

    float4 acc = make_float4(0.f, 0.f, 0.f, 0.f);
    for (int e = g; e < cnt; e += 16) {            // cnt~13 -> 1 round
        float4 v = *(const float4*)(g_P + se[e] + l * 4);
        acc.x += v.x; acc.y += v.y; acc.z += v.z; acc.w += v.w;
    }
    sp[g][l] = acc;
    __syncthreads();

    if (g == 0) {
        float4 s = sp[0][l];
#pragma unroll
        for (int q = 1; q < 16; q++) {
            float4 v = sp[q][l];
            s.x += v.x; s.y += v.y; s.z += v.z; s.w += v.w;
        }
        float4 bv = ((const float4*)b)[l];
        s.x = fmaxf(s.x + bv.x, 0.f);
        s.y = fmaxf(s.y + bv.y, 0.f);
        s.z = fmaxf(s.z + bv.z, 0.f);
        s.w = fmaxf(s.w + bv.w, 0.f);
        ((float4*)(out + i * OUTD))[l] = s;
    }
}

// =============================================================================
extern "C" void kernel_launch(void* const* d_in, const int* in_sizes, int n_in,
                              void* d_out, int out_size) {
    const float* hidden = (const float*)d_in[0];
    const float* obs2   = (const float*)d_in[2];
    const float* W      = (const float*)d_in[3];
    const float* b      = (const float*)d_in[4];
    float*       out    = (float*)d_out;

    cudaFuncSetAttribute(gemm_mma_kernel, cudaFuncAttributeMaxDynamicSharedMemorySize, SMEM_DYN);

    prep_kernel<<<256, 256>>>(W);

    cudaLaunchAttribute attr[1];
    attr[0].id = cudaLaunchAttributeProgrammaticStreamSerialization;
    attr[0].val.programmaticStreamSerializationAllowed = 1;

    cudaLaunchConfig_t cfg = {};
    cfg.gridDim = dim3(N_AG / 128, KDIM / 128);   // (8, 16)
    cfg.blockDim = dim3(256);
    cfg.dynamicSmemBytes = SMEM_DYN;
    cfg.stream = 0;
    cfg.attrs = attr;
    cfg.numAttrs = 1;
    cudaLaunchKernelEx(&cfg, gemm_mma_kernel, hidden);

    cfg.gridDim = dim3(N_AG);
    cfg.blockDim = dim3(512);
    cfg.dynamicSmemBytes = 0;
    cudaLaunchKernelEx(&cfg, out_kernel, obs2, b, out);
}